// round 8
// baseline (speedup 1.0000x reference)
#include <cuda_runtime.h>
#include <cuda_fp16.h>

#define NN 50000
#define EE 800000
#define BB 2
#define TT 12
#define T2 10
#define T3 8
#define HH 16
#define ROW (BB*T2*HH)   // 320
#define CLS 2
#define WPB 8

typedef unsigned long long ull;
typedef unsigned int uint;

// ---------------- device scratch ----------------
__device__ int    g_is64;
__device__ float  g_deg[NN];
__device__ int    g_cnt[NN];
__device__ int    g_rowptr[NN + 1];
__device__ int    g_woff[NN];
__device__ int2   g_csr[EE];
__device__ float  g_h1[NN * ROW];    // 64 MB fp32 (exact Tx0 path)
__device__ __half g_h1h[NN * ROW];   // 32 MB fp16 copy (gather path)
__device__ float  g_agg[NN * ROW];   // 64 MB

// ---------------- f32x2 helpers ----------------
__device__ __forceinline__ ull pk2(float lo, float hi) {
    ull r; asm("mov.b64 %0, {%1, %2};" : "=l"(r) : "f"(lo), "f"(hi)); return r;
}
__device__ __forceinline__ void fma2(ull& d, ull a, ull b) {
    asm("fma.rn.f32x2 %0, %1, %2, %3;" : "=l"(d) : "l"(a), "l"(b), "l"(d));
}
__device__ __forceinline__ float2 upk(ull v) {
    float2 f; asm("mov.b64 {%0, %1}, %2;" : "=f"(f.x), "=f"(f.y) : "l"(v)); return f;
}

__device__ __forceinline__ int edge_val(const void* ei, int which, int e, int is64) {
    if (is64) return (int)((const long long*)ei)[(long long)which * EE + e];
    return ((const int*)ei)[which * EE + e];
}

// ---------------- init: zero + dtype detect ----------------
__global__ void k_init(const void* ei) {
    int i = blockIdx.x * blockDim.x + threadIdx.x;
    if (i == 0) {
        const int* p = (const int*)ei;
        int nz = 0;
        for (int j = 0; j < 64; j++) nz |= p[2 * j + 1];
        g_is64 = (nz == 0) ? 1 : 0;
    }
    if (i < NN) { g_deg[i] = 0.f; g_cnt[i] = 0; }
}

__global__ void k_hist(const void* __restrict__ ei, const float* __restrict__ ew) {
    int e = blockIdx.x * blockDim.x + threadIdx.x;
    int is64 = g_is64;
    if (e < EE) {
        int s = edge_val(ei, 0, e, is64);
        int d = edge_val(ei, 1, e, is64);
        atomicAdd(&g_deg[s], ew[e]);
        atomicAdd(&g_cnt[d], 1);
    }
}

__global__ void k_scan() {
    __shared__ int ss[1024];
    const int CH = (NN + 1023) / 1024;
    int t = threadIdx.x;
    int lo = t * CH;
    int hi = lo + CH; if (hi > NN) hi = NN;
    int s = 0;
    for (int i = lo; i < hi; i++) s += g_cnt[i];
    ss[t] = s;
    __syncthreads();
    for (int off = 1; off < 1024; off <<= 1) {
        int v = (t >= off) ? ss[t - off] : 0;
        __syncthreads();
        ss[t] += v;
        __syncthreads();
    }
    int run = (t == 0) ? 0 : ss[t - 1];
    for (int i = lo; i < hi; i++) {
        int c = g_cnt[i];
        g_rowptr[i] = run;
        g_woff[i]   = run;
        run += c;
    }
    if (t == 1023) g_rowptr[NN] = ss[1023];
}

__global__ void k_scatter(const void* __restrict__ ei, const float* __restrict__ ew) {
    int e = blockIdx.x * blockDim.x + threadIdx.x;
    int is64 = g_is64;
    if (e < EE) {
        int s = edge_val(ei, 0, e, is64);
        int d = edge_val(ei, 1, e, is64);
        float ds = g_deg[s], dd = g_deg[d];
        float qs = (ds > 0.f) ? rsqrtf(fmaxf(ds, 1e-12f)) : 0.f;
        float qd = (dd > 0.f) ? rsqrtf(fmaxf(dd, 1e-12f)) : 0.f;
        float nm = -qs * ew[e] * qd;
        int pos = atomicAdd(&g_woff[d], 1);
        g_csr[pos] = make_int2(s, __float_as_int(nm));
    }
}

// ---------------- TC1 (writes fp32 h1 + fp16 copy) ----------------
__global__ void k_tc1(const float* __restrict__ x,
                      const float* __restrict__ wP, const float* __restrict__ bP,
                      const float* __restrict__ wQ, const float* __restrict__ bQ,
                      const float* __restrict__ wR, const float* __restrict__ bR) {
    __shared__ float sw[192];
    int tid = threadIdx.x;
    if (tid < 48)       sw[tid] = wP[tid];
    else if (tid < 96)  sw[tid] = wQ[tid - 48];
    else if (tid < 144) sw[tid] = wR[tid - 96];
    else if (tid < 160) sw[tid] = bP[tid - 144];
    else if (tid < 176) sw[tid] = bQ[tid - 160];
    else if (tid < 192) sw[tid] = bR[tid - 176];
    __syncthreads();

    int g = blockIdx.x * blockDim.x + tid;
    if (g >= BB * T2 * NN) return;
    int n  = g % NN;
    int bt = g / NN;
    int b  = bt / T2;
    int t  = bt % T2;

    float xv0 = x[(b * TT + t    ) * NN + n];
    float xv1 = x[(b * TT + t + 1) * NN + n];
    float xv2 = x[(b * TT + t + 2) * NN + n];

    float out[16];
#pragma unroll
    for (int h = 0; h < 16; h++) {
        float p = sw[144 + h] + xv0 * sw[h]      + xv1 * sw[16 + h]  + xv2 * sw[32 + h];
        float q = sw[160 + h] + xv0 * sw[48 + h] + xv1 * sw[64 + h]  + xv2 * sw[80 + h];
        float r = sw[176 + h] + xv0 * sw[96 + h] + xv1 * sw[112 + h] + xv2 * sw[128 + h];
        float sg = 1.f / (1.f + __expf(-q));
        float v  = p * sg + r;
        out[h] = (v > 0.f) ? v : 0.f;
    }
    float4* dst = (float4*)&g_h1[(size_t)n * ROW + bt * 16];
#pragma unroll
    for (int j = 0; j < 4; j++)
        dst[j] = make_float4(out[4*j], out[4*j+1], out[4*j+2], out[4*j+3]);

    // fp16 copy: 16 halves = 32 B = 2 x uint4
    __half2 hh[8];
#pragma unroll
    for (int j = 0; j < 8; j++)
        hh[j] = __floats2half2_rn(out[2*j], out[2*j+1]);
    uint4* dh = (uint4*)&g_h1h[(size_t)n * ROW + bt * 16];
    uint* hw = (uint*)hh;
    dh[0] = make_uint4(hw[0], hw[1], hw[2], hw[3]);
    dh[1] = make_uint4(hw[4], hw[5], hw[6], hw[7]);
}

// ---------------- gather: lean, fp16 loads, fp32 f32x2 accum ----------------
__global__ void __launch_bounds__(256)
k_gather() {
    int warp = (blockIdx.x * blockDim.x + threadIdx.x) >> 5;
    int lane = threadIdx.x & 31;
    if (warp >= NN) return;
    int beg = g_rowptr[warp];
    int end = g_rowptr[warp + 1];

    ull acc[5];
#pragma unroll
    for (int j = 0; j < 5; j++) acc[j] = 0ull;

    int i = beg;
    for (; i + 2 <= end; i += 2) {
        int2 e0 = g_csr[i];
        int2 e1 = g_csr[i + 1];
        const uint* p0 = (const uint*)&g_h1h[(size_t)e0.x * ROW] + lane;  // uint = half2
        const uint* p1 = (const uint*)&g_h1h[(size_t)e1.x * ROW] + lane;
        uint v0[5], v1[5];
#pragma unroll
        for (int j = 0; j < 5; j++) v0[j] = p0[j * 32];
#pragma unroll
        for (int j = 0; j < 5; j++) v1[j] = p1[j * 32];
        float n0 = __int_as_float(e0.y);
        float n1 = __int_as_float(e1.y);
        ull nm0 = pk2(n0, n0);
        ull nm1 = pk2(n1, n1);
#pragma unroll
        for (int j = 0; j < 5; j++) {
            float2 f0 = __half22float2(*(const __half2*)&v0[j]);
            float2 f1 = __half22float2(*(const __half2*)&v1[j]);
            fma2(acc[j], nm0, pk2(f0.x, f0.y));
            fma2(acc[j], nm1, pk2(f1.x, f1.y));
        }
    }
    if (i < end) {
        int2 e0 = g_csr[i];
        const uint* p0 = (const uint*)&g_h1h[(size_t)e0.x * ROW] + lane;
        float n0 = __int_as_float(e0.y);
        ull nm0 = pk2(n0, n0);
#pragma unroll
        for (int j = 0; j < 5; j++) {
            uint v = p0[j * 32];
            float2 f = __half22float2(*(const __half2*)&v);
            fma2(acc[j], nm0, pk2(f.x, f.y));
        }
    }
    ull* q = (ull*)&g_agg[(size_t)warp * ROW] + lane;   // same pair layout: channels (64j+2l, +1)
#pragma unroll
    for (int j = 0; j < 5; j++) q[j * 32] = acc[j];
}

// ---------------- combined: cheb + TC2 + mean + linear (R6 proven) ----------
struct alignas(16) SmemC {
    float sAgg[WPB][ROW];
    float sH1[WPB][ROW];
    float sH2[WPB][ROW];
    ull   swP2[768], swQ2[768], swR2[768];
    float sw0[256], sw1[256];
    float sb[16], sbP[16], sbQ[16], sbR[16];
    float slw[32], slb[2];
};

__global__ void __launch_bounds__(WPB * 32)
k_combined(const float* __restrict__ chw, const float* __restrict__ chb,
           const float* __restrict__ wP, const float* __restrict__ bP,
           const float* __restrict__ wQ, const float* __restrict__ bQ,
           const float* __restrict__ wR, const float* __restrict__ bR,
           const float* __restrict__ lw, const float* __restrict__ lb,
           float* __restrict__ out) {
    extern __shared__ unsigned char smem_raw[];
    SmemC* S = reinterpret_cast<SmemC*>(smem_raw);
    int tid = threadIdx.x;

    for (int i = tid; i < 768; i += WPB * 32) {
        float p = wP[i], q = wQ[i], r = wR[i];
        S->swP2[i] = pk2(p, p);
        S->swQ2[i] = pk2(q, q);
        S->swR2[i] = pk2(r, r);
    }
    for (int i = tid; i < 256; i += WPB * 32) {
        S->sw0[i] = chw[i];
        S->sw1[i] = chw[256 + i];
    }
    if (tid < 16) {
        S->sb[tid]  = chb[tid];
        S->sbP[tid] = bP[tid];
        S->sbQ[tid] = bQ[tid];
        S->sbR[tid] = bR[tid];
    }
    if (tid < 32) S->slw[tid] = lw[tid];
    if (tid < 2)  S->slb[tid] = lb[tid];
    __syncthreads();

    int w    = tid >> 5;
    int lane = tid & 31;
    int node = blockIdx.x * WPB + w;
    if (node >= NN) return;

    {
        const float4* s1 = (const float4*)&g_h1[(size_t)node * ROW];
        const float4* sa = (const float4*)&g_agg[(size_t)node * ROW];
        float4* d1 = (float4*)S->sH1[w];
        float4* da = (float4*)S->sAgg[w];
        for (int i = lane; i < 80; i += 32) { d1[i] = s1[i]; da[i] = sa[i]; }
    }
    __syncwarp();

    {
        int h  = lane & 15;
        int g2 = lane >> 4;
        float w0r[16], w1r[16];
#pragma unroll
        for (int c = 0; c < 16; c++) { w0r[c] = S->sw0[c * 16 + h]; w1r[c] = S->sw1[c * 16 + h]; }
        float bias = S->sb[h];
        const float* h1w = S->sH1[w];
        float* aggw = S->sAgg[w];
        float* h2w  = S->sH2[w];
#pragma unroll
        for (int k = 0; k < 10; k++) {
            int bt = 2 * k + g2;
            const float4* x1 = (const float4*)&h1w[bt * 16];
            const float4* xa = (const float4*)&aggw[bt * 16];
            float a = bias;
#pragma unroll
            for (int j = 0; j < 4; j++) {
                float4 v = x1[j];
                float4 u = xa[j];
                a = fmaf(v.x, w0r[4*j+0], a); a = fmaf(u.x, w1r[4*j+0], a);
                a = fmaf(v.y, w0r[4*j+1], a); a = fmaf(u.y, w1r[4*j+1], a);
                a = fmaf(v.z, w0r[4*j+2], a); a = fmaf(u.z, w1r[4*j+2], a);
                a = fmaf(v.w, w0r[4*j+3], a); a = fmaf(u.w, w1r[4*j+3], a);
            }
            h2w[bt * 16 + h] = (a > 0.f) ? a : 0.f;
        }
    }
    __syncwarp();

    {
        int p = lane >> 4;
        int h = lane & 15;
        const float* xs = &S->sH2[w][p * (T2 * HH)];

        ull accP2[4], accQ2[4], accR2[4];
        {
            float vb = S->sbP[h]; ull b2 = pk2(vb, vb);
#pragma unroll
            for (int j = 0; j < 4; j++) accP2[j] = b2;
            vb = S->sbQ[h]; b2 = pk2(vb, vb);
#pragma unroll
            for (int j = 0; j < 4; j++) accQ2[j] = b2;
            vb = S->sbR[h]; b2 = pk2(vb, vb);
#pragma unroll
            for (int j = 0; j < 4; j++) accR2[j] = b2;
        }

#pragma unroll
        for (int c = 0; c < 16; c++) {
            float xr[10];
#pragma unroll
            for (int t = 0; t < 10; t++) xr[t] = xs[t * 16 + c];
            ull xp[5], xq[4];
#pragma unroll
            for (int j = 0; j < 5; j++) xp[j] = pk2(xr[2*j], xr[2*j+1]);
#pragma unroll
            for (int j = 0; j < 4; j++) xq[j] = pk2(xr[2*j+1], xr[2*j+2]);

            {
                ull wp = S->swP2[c * 16 + h];
                ull wq = S->swQ2[c * 16 + h];
                ull wr = S->swR2[c * 16 + h];
#pragma unroll
                for (int j = 0; j < 4; j++) {
                    fma2(accP2[j], xp[j], wp);
                    fma2(accQ2[j], xp[j], wq);
                    fma2(accR2[j], xp[j], wr);
                }
            }
            {
                ull wp = S->swP2[256 + c * 16 + h];
                ull wq = S->swQ2[256 + c * 16 + h];
                ull wr = S->swR2[256 + c * 16 + h];
#pragma unroll
                for (int j = 0; j < 4; j++) {
                    fma2(accP2[j], xq[j], wp);
                    fma2(accQ2[j], xq[j], wq);
                    fma2(accR2[j], xq[j], wr);
                }
            }
            {
                ull wp = S->swP2[512 + c * 16 + h];
                ull wq = S->swQ2[512 + c * 16 + h];
                ull wr = S->swR2[512 + c * 16 + h];
#pragma unroll
                for (int j = 0; j < 4; j++) {
                    fma2(accP2[j], xp[j + 1], wp);
                    fma2(accQ2[j], xp[j + 1], wq);
                    fma2(accR2[j], xp[j + 1], wr);
                }
            }
        }

        float ms = 0.f;
#pragma unroll
        for (int j = 0; j < 4; j++) {
            float2 P = upk(accP2[j]), Q = upk(accQ2[j]), R = upk(accR2[j]);
            float s0 = 1.f / (1.f + __expf(-Q.x));
            float v0 = P.x * s0 + R.x;
            ms += (v0 > 0.f) ? v0 : 0.f;
            float s1 = 1.f / (1.f + __expf(-Q.y));
            float v1 = P.y * s1 + R.y;
            ms += (v1 > 0.f) ? v1 : 0.f;
        }
        ms *= (1.f / (float)T3);

        float c0 = ms * S->slw[h * 2 + 0];
        float c1 = ms * S->slw[h * 2 + 1];
#pragma unroll
        for (int o = 8; o >= 1; o >>= 1) {
            c0 += __shfl_xor_sync(0xffffffffu, c0, o);
            c1 += __shfl_xor_sync(0xffffffffu, c1, o);
        }
        if (h == 0) {
            out[((size_t)p * NN + node) * CLS + 0] = c0 + S->slb[0];
            out[((size_t)p * NN + node) * CLS + 1] = c1 + S->slb[1];
        }
    }
}

// ---------------- launch ----------------
extern "C" void kernel_launch(void* const* d_in, const int* in_sizes, int n_in,
                              void* d_out, int out_size) {
    const float* x  = (const float*)d_in[0];
    const void*  ei = d_in[1];
    const float* ew = (const float*)d_in[2];

    int i_tc1 = 3, i_tc2, i_cheb, i_lin;
    if (in_sizes[9] == 512) { i_cheb = 9; i_tc2 = 11; i_lin = 17; }
    else                    { i_tc2 = 9; i_cheb = 15; i_lin = 17; }

    const float* t1Pw = (const float*)d_in[i_tc1 + 0];
    const float* t1Pb = (const float*)d_in[i_tc1 + 1];
    const float* t1Qw = (const float*)d_in[i_tc1 + 2];
    const float* t1Qb = (const float*)d_in[i_tc1 + 3];
    const float* t1Rw = (const float*)d_in[i_tc1 + 4];
    const float* t1Rb = (const float*)d_in[i_tc1 + 5];
    const float* t2Pw = (const float*)d_in[i_tc2 + 0];
    const float* t2Pb = (const float*)d_in[i_tc2 + 1];
    const float* t2Qw = (const float*)d_in[i_tc2 + 2];
    const float* t2Qb = (const float*)d_in[i_tc2 + 3];
    const float* t2Rw = (const float*)d_in[i_tc2 + 4];
    const float* t2Rb = (const float*)d_in[i_tc2 + 5];
    const float* chw  = (const float*)d_in[i_cheb + 0];
    const float* chb  = (const float*)d_in[i_cheb + 1];
    const float* lw   = (const float*)d_in[i_lin + 0];
    const float* lb   = (const float*)d_in[i_lin + 1];
    float* out = (float*)d_out;

    const int TB = 256;
    static int smem_set = 0;
    int smem_bytes = (int)sizeof(SmemC);
    if (!smem_set) {
        cudaFuncSetAttribute(k_combined, cudaFuncAttributeMaxDynamicSharedMemorySize, smem_bytes);
        smem_set = 1;
    }

    k_init<<<(NN + TB - 1) / TB, TB>>>(ei);
    k_hist<<<(EE + TB - 1) / TB, TB>>>(ei, ew);
    k_scan<<<1, 1024>>>();
    k_scatter<<<(EE + TB - 1) / TB, TB>>>(ei, ew);
    k_tc1<<<(BB * T2 * NN + TB - 1) / TB, TB>>>(x, t1Pw, t1Pb, t1Qw, t1Qb, t1Rw, t1Rb);
    k_gather<<<(NN * 32 + TB - 1) / TB, TB>>>();
    k_combined<<<(NN + WPB - 1) / WPB, WPB * 32, smem_bytes>>>(
        chw, chb, t2Pw, t2Pb, t2Qw, t2Qb, t2Rw, t2Rb, lw, lb, out);
}

// round 9
// speedup vs baseline: 1.5163x; 1.5163x over previous
#include <cuda_runtime.h>

#define NN 50000
#define EE 800000
#define BB 2
#define TT 12
#define T2 10
#define T3 8
#define HH 16
#define ROW (BB*T2*HH)   // 320
#define CLS 2
#define WPB 8

typedef unsigned long long ull;

// ---------------- device scratch ----------------
__device__ int   g_is64;
__device__ float g_deg[NN];
__device__ int   g_cnt[NN];
__device__ int   g_rowptr[NN + 1];
__device__ int   g_woff[NN];
__device__ int2  g_csr[EE];
__device__ float g_h1[NN * ROW];    // 64 MB
__device__ float g_agg[NN * ROW];   // 64 MB

// ---------------- f32x2 helpers ----------------
__device__ __forceinline__ ull pk2(float lo, float hi) {
    ull r; asm("mov.b64 %0, {%1, %2};" : "=l"(r) : "f"(lo), "f"(hi)); return r;
}
__device__ __forceinline__ void fma2(ull& d, ull a, ull b) {
    asm("fma.rn.f32x2 %0, %1, %2, %3;" : "=l"(d) : "l"(a), "l"(b), "l"(d));
}
__device__ __forceinline__ float2 upk(ull v) {
    float2 f; asm("mov.b64 {%0, %1}, %2;" : "=f"(f.x), "=f"(f.y) : "l"(v)); return f;
}

__device__ __forceinline__ int edge_val(const void* ei, int which, int e, int is64) {
    if (is64) return (int)((const long long*)ei)[(long long)which * EE + e];
    return ((const int*)ei)[which * EE + e];
}

// ---------------- init: zero + dtype detect ----------------
__global__ void k_init(const void* ei) {
    int i = blockIdx.x * blockDim.x + threadIdx.x;
    if (i == 0) {
        const int* p = (const int*)ei;
        int nz = 0;
        for (int j = 0; j < 64; j++) nz |= p[2 * j + 1];
        g_is64 = (nz == 0) ? 1 : 0;
    }
    if (i < NN) { g_deg[i] = 0.f; g_cnt[i] = 0; }
}

__global__ void k_hist(const void* __restrict__ ei, const float* __restrict__ ew) {
    int e = blockIdx.x * blockDim.x + threadIdx.x;
    int is64 = g_is64;
    if (e < EE) {
        int s = edge_val(ei, 0, e, is64);
        int d = edge_val(ei, 1, e, is64);
        atomicAdd(&g_deg[s], ew[e]);
        atomicAdd(&g_cnt[d], 1);
    }
}

__global__ void k_scan() {
    __shared__ int ss[1024];
    const int CH = (NN + 1023) / 1024;
    int t = threadIdx.x;
    int lo = t * CH;
    int hi = lo + CH; if (hi > NN) hi = NN;
    int s = 0;
    for (int i = lo; i < hi; i++) s += g_cnt[i];
    ss[t] = s;
    __syncthreads();
    for (int off = 1; off < 1024; off <<= 1) {
        int v = (t >= off) ? ss[t - off] : 0;
        __syncthreads();
        ss[t] += v;
        __syncthreads();
    }
    int run = (t == 0) ? 0 : ss[t - 1];
    for (int i = lo; i < hi; i++) {
        int c = g_cnt[i];
        g_rowptr[i] = run;
        g_woff[i]   = run;
        run += c;
    }
    if (t == 1023) g_rowptr[NN] = ss[1023];
}

__global__ void k_scatter(const void* __restrict__ ei, const float* __restrict__ ew) {
    int e = blockIdx.x * blockDim.x + threadIdx.x;
    int is64 = g_is64;
    if (e < EE) {
        int s = edge_val(ei, 0, e, is64);
        int d = edge_val(ei, 1, e, is64);
        float ds = g_deg[s], dd = g_deg[d];
        float qs = (ds > 0.f) ? rsqrtf(fmaxf(ds, 1e-12f)) : 0.f;
        float qd = (dd > 0.f) ? rsqrtf(fmaxf(dd, 1e-12f)) : 0.f;
        float nm = -qs * ew[e] * qd;
        int pos = atomicAdd(&g_woff[d], 1);
        g_csr[pos] = make_int2(s, __float_as_int(nm));
    }
}

// ---------------- TC1 ----------------
__global__ void k_tc1(const float* __restrict__ x,
                      const float* __restrict__ wP, const float* __restrict__ bP,
                      const float* __restrict__ wQ, const float* __restrict__ bQ,
                      const float* __restrict__ wR, const float* __restrict__ bR) {
    __shared__ float sw[192];
    int tid = threadIdx.x;
    if (tid < 48)       sw[tid] = wP[tid];
    else if (tid < 96)  sw[tid] = wQ[tid - 48];
    else if (tid < 144) sw[tid] = wR[tid - 96];
    else if (tid < 160) sw[tid] = bP[tid - 144];
    else if (tid < 176) sw[tid] = bQ[tid - 160];
    else if (tid < 192) sw[tid] = bR[tid - 176];
    __syncthreads();

    int g = blockIdx.x * blockDim.x + tid;
    if (g >= BB * T2 * NN) return;
    int n  = g % NN;
    int bt = g / NN;
    int b  = bt / T2;
    int t  = bt % T2;

    float xv0 = x[(b * TT + t    ) * NN + n];
    float xv1 = x[(b * TT + t + 1) * NN + n];
    float xv2 = x[(b * TT + t + 2) * NN + n];

    float out[16];
#pragma unroll
    for (int h = 0; h < 16; h++) {
        float p = sw[144 + h] + xv0 * sw[h]      + xv1 * sw[16 + h]  + xv2 * sw[32 + h];
        float q = sw[160 + h] + xv0 * sw[48 + h] + xv1 * sw[64 + h]  + xv2 * sw[80 + h];
        float r = sw[176 + h] + xv0 * sw[96 + h] + xv1 * sw[112 + h] + xv2 * sw[128 + h];
        float sg = 1.f / (1.f + __expf(-q));
        float v  = p * sg + r;
        out[h] = (v > 0.f) ? v : 0.f;
    }
    float4* dst = (float4*)&g_h1[(size_t)n * ROW + bt * 16];
#pragma unroll
    for (int j = 0; j < 4; j++)
        dst[j] = make_float4(out[4*j], out[4*j+1], out[4*j+2], out[4*j+3]);
}

// ---------------- gather: lean fp32 f32x2, 2-edge unroll, streaming hints ----
__global__ void __launch_bounds__(256)
k_gather() {
    int warp = (blockIdx.x * blockDim.x + threadIdx.x) >> 5;
    int lane = threadIdx.x & 31;
    if (warp >= NN) return;
    int beg = g_rowptr[warp];
    int end = g_rowptr[warp + 1];

    ull acc[5];
#pragma unroll
    for (int j = 0; j < 5; j++) acc[j] = 0ull;

    int i = beg;
    for (; i + 2 <= end; i += 2) {
        int2 e0 = __ldcs(&g_csr[i]);
        int2 e1 = __ldcs(&g_csr[i + 1]);
        const ull* p0 = (const ull*)&g_h1[(size_t)e0.x * ROW] + lane;
        const ull* p1 = (const ull*)&g_h1[(size_t)e1.x * ROW] + lane;
        ull v0[5], v1[5];
#pragma unroll
        for (int j = 0; j < 5; j++) v0[j] = p0[j * 32];
#pragma unroll
        for (int j = 0; j < 5; j++) v1[j] = p1[j * 32];
        float n0 = __int_as_float(e0.y);
        float n1 = __int_as_float(e1.y);
        ull nm0 = pk2(n0, n0);
        ull nm1 = pk2(n1, n1);
#pragma unroll
        for (int j = 0; j < 5; j++) { fma2(acc[j], nm0, v0[j]); fma2(acc[j], nm1, v1[j]); }
    }
    if (i < end) {
        int2 e0 = __ldcs(&g_csr[i]);
        const ull* p0 = (const ull*)&g_h1[(size_t)e0.x * ROW] + lane;
        float n0 = __int_as_float(e0.y);
        ull nm0 = pk2(n0, n0);
#pragma unroll
        for (int j = 0; j < 5; j++) { ull v = p0[j * 32]; fma2(acc[j], nm0, v); }
    }
    // streaming stores: do not let agg evict h1 from L2
    ull* q = (ull*)&g_agg[(size_t)warp * ROW] + lane;
#pragma unroll
    for (int j = 0; j < 5; j++) __stcs(&q[j * 32], acc[j]);
}

// ---------------- combined: cheb + TC2 + mean + linear ----------------
struct alignas(16) SmemC {
    float sAgg[WPB][ROW];
    float sH1[WPB][ROW];
    float sH2[WPB][ROW];
    ull   swP2[768], swQ2[768], swR2[768];
    float sw0[256], sw1[256];
    float sb[16], sbP[16], sbQ[16], sbR[16];
    float slw[32], slb[2];
};

__global__ void __launch_bounds__(WPB * 32)
k_combined(const float* __restrict__ chw, const float* __restrict__ chb,
           const float* __restrict__ wP, const float* __restrict__ bP,
           const float* __restrict__ wQ, const float* __restrict__ bQ,
           const float* __restrict__ wR, const float* __restrict__ bR,
           const float* __restrict__ lw, const float* __restrict__ lb,
           float* __restrict__ out) {
    extern __shared__ unsigned char smem_raw[];
    SmemC* S = reinterpret_cast<SmemC*>(smem_raw);
    int tid = threadIdx.x;

    for (int i = tid; i < 768; i += WPB * 32) {
        float p = wP[i], q = wQ[i], r = wR[i];
        S->swP2[i] = pk2(p, p);
        S->swQ2[i] = pk2(q, q);
        S->swR2[i] = pk2(r, r);
    }
    for (int i = tid; i < 256; i += WPB * 32) {
        S->sw0[i] = chw[i];
        S->sw1[i] = chw[256 + i];
    }
    if (tid < 16) {
        S->sb[tid]  = chb[tid];
        S->sbP[tid] = bP[tid];
        S->sbQ[tid] = bQ[tid];
        S->sbR[tid] = bR[tid];
    }
    if (tid < 32) S->slw[tid] = lw[tid];
    if (tid < 2)  S->slb[tid] = lb[tid];
    __syncthreads();

    int w    = tid >> 5;
    int lane = tid & 31;
    int node = blockIdx.x * WPB + w;
    if (node >= NN) return;

    // stage h1/agg rows (read-once: streaming loads)
    {
        const float4* s1 = (const float4*)&g_h1[(size_t)node * ROW];
        const float4* sa = (const float4*)&g_agg[(size_t)node * ROW];
        float4* d1 = (float4*)S->sH1[w];
        float4* da = (float4*)S->sAgg[w];
        for (int i = lane; i < 80; i += 32) { d1[i] = __ldcs(&s1[i]); da[i] = __ldcs(&sa[i]); }
    }
    __syncwarp();

    // cheb combine h2 = relu(h1@W0 + agg@W1 + b)
    {
        int h  = lane & 15;
        int g2 = lane >> 4;
        float w0r[16], w1r[16];
#pragma unroll
        for (int c = 0; c < 16; c++) { w0r[c] = S->sw0[c * 16 + h]; w1r[c] = S->sw1[c * 16 + h]; }
        float bias = S->sb[h];
        const float* h1w = S->sH1[w];
        float* aggw = S->sAgg[w];
        float* h2w  = S->sH2[w];
#pragma unroll
        for (int k = 0; k < 10; k++) {
            int bt = 2 * k + g2;
            const float4* x1 = (const float4*)&h1w[bt * 16];
            const float4* xa = (const float4*)&aggw[bt * 16];
            float a = bias;
#pragma unroll
            for (int j = 0; j < 4; j++) {
                float4 v = x1[j];
                float4 u = xa[j];
                a = fmaf(v.x, w0r[4*j+0], a); a = fmaf(u.x, w1r[4*j+0], a);
                a = fmaf(v.y, w0r[4*j+1], a); a = fmaf(u.y, w1r[4*j+1], a);
                a = fmaf(v.z, w0r[4*j+2], a); a = fmaf(u.z, w1r[4*j+2], a);
                a = fmaf(v.w, w0r[4*j+3], a); a = fmaf(u.w, w1r[4*j+3], a);
            }
            h2w[bt * 16 + h] = (a > 0.f) ? a : 0.f;
        }
    }
    __syncwarp();

    // TC2 (f32x2 over t'-pairs) + mean + linear
    {
        int p = lane >> 4;
        int h = lane & 15;
        const float* xs = &S->sH2[w][p * (T2 * HH)];

        ull accP2[4], accQ2[4], accR2[4];
        {
            float vb = S->sbP[h]; ull b2 = pk2(vb, vb);
#pragma unroll
            for (int j = 0; j < 4; j++) accP2[j] = b2;
            vb = S->sbQ[h]; b2 = pk2(vb, vb);
#pragma unroll
            for (int j = 0; j < 4; j++) accQ2[j] = b2;
            vb = S->sbR[h]; b2 = pk2(vb, vb);
#pragma unroll
            for (int j = 0; j < 4; j++) accR2[j] = b2;
        }

#pragma unroll
        for (int c = 0; c < 16; c++) {
            float xr[10];
#pragma unroll
            for (int t = 0; t < 10; t++) xr[t] = xs[t * 16 + c];
            ull xp[5], xq[4];
#pragma unroll
            for (int j = 0; j < 5; j++) xp[j] = pk2(xr[2*j], xr[2*j+1]);
#pragma unroll
            for (int j = 0; j < 4; j++) xq[j] = pk2(xr[2*j+1], xr[2*j+2]);

            {
                ull wp = S->swP2[c * 16 + h];
                ull wq = S->swQ2[c * 16 + h];
                ull wr = S->swR2[c * 16 + h];
#pragma unroll
                for (int j = 0; j < 4; j++) {
                    fma2(accP2[j], xp[j], wp);
                    fma2(accQ2[j], xp[j], wq);
                    fma2(accR2[j], xp[j], wr);
                }
            }
            {
                ull wp = S->swP2[256 + c * 16 + h];
                ull wq = S->swQ2[256 + c * 16 + h];
                ull wr = S->swR2[256 + c * 16 + h];
#pragma unroll
                for (int j = 0; j < 4; j++) {
                    fma2(accP2[j], xq[j], wp);
                    fma2(accQ2[j], xq[j], wq);
                    fma2(accR2[j], xq[j], wr);
                }
            }
            {
                ull wp = S->swP2[512 + c * 16 + h];
                ull wq = S->swQ2[512 + c * 16 + h];
                ull wr = S->swR2[512 + c * 16 + h];
#pragma unroll
                for (int j = 0; j < 4; j++) {
                    fma2(accP2[j], xp[j + 1], wp);
                    fma2(accQ2[j], xp[j + 1], wq);
                    fma2(accR2[j], xp[j + 1], wr);
                }
            }
        }

        float ms = 0.f;
#pragma unroll
        for (int j = 0; j < 4; j++) {
            float2 P = upk(accP2[j]), Q = upk(accQ2[j]), R = upk(accR2[j]);
            float s0 = 1.f / (1.f + __expf(-Q.x));
            float v0 = P.x * s0 + R.x;
            ms += (v0 > 0.f) ? v0 : 0.f;
            float s1 = 1.f / (1.f + __expf(-Q.y));
            float v1 = P.y * s1 + R.y;
            ms += (v1 > 0.f) ? v1 : 0.f;
        }
        ms *= (1.f / (float)T3);

        float c0 = ms * S->slw[h * 2 + 0];
        float c1 = ms * S->slw[h * 2 + 1];
#pragma unroll
        for (int o = 8; o >= 1; o >>= 1) {
            c0 += __shfl_xor_sync(0xffffffffu, c0, o);
            c1 += __shfl_xor_sync(0xffffffffu, c1, o);
        }
        if (h == 0) {
            out[((size_t)p * NN + node) * CLS + 0] = c0 + S->slb[0];
            out[((size_t)p * NN + node) * CLS + 1] = c1 + S->slb[1];
        }
    }
}

// ---------------- launch ----------------
extern "C" void kernel_launch(void* const* d_in, const int* in_sizes, int n_in,
                              void* d_out, int out_size) {
    const float* x  = (const float*)d_in[0];
    const void*  ei = d_in[1];
    const float* ew = (const float*)d_in[2];

    int i_tc1 = 3, i_tc2, i_cheb, i_lin;
    if (in_sizes[9] == 512) { i_cheb = 9; i_tc2 = 11; i_lin = 17; }
    else                    { i_tc2 = 9; i_cheb = 15; i_lin = 17; }

    const float* t1Pw = (const float*)d_in[i_tc1 + 0];
    const float* t1Pb = (const float*)d_in[i_tc1 + 1];
    const float* t1Qw = (const float*)d_in[i_tc1 + 2];
    const float* t1Qb = (const float*)d_in[i_tc1 + 3];
    const float* t1Rw = (const float*)d_in[i_tc1 + 4];
    const float* t1Rb = (const float*)d_in[i_tc1 + 5];
    const float* t2Pw = (const float*)d_in[i_tc2 + 0];
    const float* t2Pb = (const float*)d_in[i_tc2 + 1];
    const float* t2Qw = (const float*)d_in[i_tc2 + 2];
    const float* t2Qb = (const float*)d_in[i_tc2 + 3];
    const float* t2Rw = (const float*)d_in[i_tc2 + 4];
    const float* t2Rb = (const float*)d_in[i_tc2 + 5];
    const float* chw  = (const float*)d_in[i_cheb + 0];
    const float* chb  = (const float*)d_in[i_cheb + 1];
    const float* lw   = (const float*)d_in[i_lin + 0];
    const float* lb   = (const float*)d_in[i_lin + 1];
    float* out = (float*)d_out;

    const int TB = 256;
    static int smem_set = 0;
    int smem_bytes = (int)sizeof(SmemC);
    if (!smem_set) {
        cudaFuncSetAttribute(k_combined, cudaFuncAttributeMaxDynamicSharedMemorySize, smem_bytes);
        smem_set = 1;
    }

    k_init<<<(NN + TB - 1) / TB, TB>>>(ei);
    k_hist<<<(EE + TB - 1) / TB, TB>>>(ei, ew);
    k_scan<<<1, 1024>>>();
    k_scatter<<<(EE + TB - 1) / TB, TB>>>(ei, ew);
    k_tc1<<<(BB * T2 * NN + TB - 1) / TB, TB>>>(x, t1Pw, t1Pb, t1Qw, t1Qb, t1Rw, t1Rb);
    k_gather<<<(NN * 32 + TB - 1) / TB, TB>>>();
    k_combined<<<(NN + WPB - 1) / WPB, WPB * 32, smem_bytes>>>(
        chw, chb, t2Pw, t2Pb, t2Qw, t2Qb, t2Rw, t2Rb, lw, lb, out);
}